// round 4
// baseline (speedup 1.0000x reference)
#include <cuda_runtime.h>
#include <math.h>

#define N_NODES 12288
#define N_EDGES 196608
#define F_IN    1433
#define H1      32
#define H2      16
#define NCLS    7

#define GCHUNK   128          // K chunk staged in smem
#define GSTRIDE  132          // padded W stride (33 granules, odd -> conflict-free LDS.128)
#define NCHUNK   12           // ceil(1433/128)
#define ROWS_PB  32           // rows per block (8 warps x 4 rows)

// ---- scratch (static device globals; no allocation allowed) ----
__device__ float g_xw  [N_NODES * H1];   // x @ W1
__device__ float g_h   [N_NODES * H1];   // relu(A_norm @ xw + b1)
__device__ float g_agg1[N_NODES * H1];   // GCN neighbor accumulation (edges only)
__device__ float g_agg2[N_NODES * H1];   // SAGE sum over h[dst] grouped by src
__device__ float g_deg [N_NODES];
__device__ float g_cnt [N_NODES];
__device__ float g_dis [N_NODES];
__device__ int   g_row [N_EDGES];        // decoded edge_index[0]
__device__ int   g_col [N_EDGES];        // decoded edge_index[1]

// packed f32x2 fma: d = a*b + d  (ptxas never emits FFMA2 from C++; PTX path works on sm_10x)
#define FFMA2(acc, a, b) \
    asm("fma.rn.f32x2 %0, %1, %2, %0;" : "+l"(acc) : "l"(a), "l"(b))

// ---- K1: init scratch ----
__global__ void k_init() {
    int i = blockIdx.x * blockDim.x + threadIdx.x;
    if (i < N_NODES * H1) {
        g_agg1[i] = 0.f; g_agg2[i] = 0.f;
    }
    if (i < N_NODES) {
        g_deg[i] = 1.f;   // self loop contributes 1 to deg (col includes loops)
        g_cnt[i] = 0.f;
    }
}

// ---- K2: probe dtype per-block + decode indices + degree/count atomics ----
// int64 little-endian high words (odd int32 slots) are all zero (ids < 12288);
// int32 layout has random node ids there -> any nonzero means int32.
__global__ void k_decode(const int* __restrict__ ei32) {
    int v = ei32[2 * threadIdx.x + 1] | ei32[2 * threadIdx.x + 513];
    int is64 = !__syncthreads_or(v != 0);   // uniform across all blocks

    int e = blockIdx.x * blockDim.x + threadIdx.x;
    if (e >= N_EDGES) return;
    int r, c;
    if (is64) {
        r = ei32[2 * e];                 // low word of int64 edge_index[0][e]
        c = ei32[2 * (N_EDGES + e)];     // low word of int64 edge_index[1][e]
    } else {
        r = ei32[e];
        c = ei32[N_EDGES + e];
    }
    g_row[e] = r;
    g_col[e] = c;
    atomicAdd(&g_deg[c], 1.f);
    atomicAdd(&g_cnt[r], 1.f);
}

// ---- K3: xw = x @ W1 (M=12288, K=1433, N=32) ----
// Block: 256 thr / 8 warps, 32 rows. lane = output column, warp owns 4 rows.
// x tile + transposed W chunk in smem; packed FFMA2 inner loop; no atomics.
__global__ void __launch_bounds__(256) k_gemm1(const float* __restrict__ x,
                                               const float* __restrict__ W1) {
    __shared__ float sx [ROWS_PB * GCHUNK];     // 16 KB, x tile
    __shared__ float swt[H1 * GSTRIDE];         // 16.5 KB, W chunk transposed [col][k]

    const int tid  = threadIdx.x;
    const int wid  = tid >> 5;
    const int lane = tid & 31;
    const int row0 = blockIdx.x * ROWS_PB;

    unsigned long long acc01[4] = {0ull, 0ull, 0ull, 0ull};  // (k even, k odd) partials
    unsigned long long acc23[4] = {0ull, 0ull, 0ull, 0ull};

    for (int ch = 0; ch < NCHUNK; ch++) {
        const int k0   = ch * GCHUNK;
        const int klen = min(GCHUNK, F_IN - k0);

        // x tile: coalesced per row (consecutive k per consecutive thread)
        for (int i = tid; i < ROWS_PB * GCHUNK; i += 256) {
            int r = i >> 7, k = i & (GCHUNK - 1);
            sx[i] = (k < klen) ? x[(size_t)(row0 + r) * F_IN + k0 + k] : 0.f;
        }
        // W chunk: coalesced read of [k][c], transposed store swt[c][k]
        for (int i = tid; i < GCHUNK * H1; i += 256) {
            int k = i >> 5, c = i & 31;
            swt[c * GSTRIDE + k] = (k < klen) ? W1[(k0 + k) * H1 + c] : 0.f;
        }
        __syncthreads();

        const float* swl = swt + lane * GSTRIDE;
#pragma unroll 4
        for (int k4 = 0; k4 < GCHUNK / 4; k4++) {
            ulonglong2 wv = *(const ulonglong2*)(swl + k4 * 4);   // w[k..k+3][lane] packed
#pragma unroll
            for (int r = 0; r < 4; r++) {
                ulonglong2 xv = *(const ulonglong2*)(sx + ((wid << 2) + r) * GCHUNK + k4 * 4);
                FFMA2(acc01[r], xv.x, wv.x);
                FFMA2(acc23[r], xv.y, wv.y);
            }
        }
        __syncthreads();
    }

#pragma unroll
    for (int r = 0; r < 4; r++) {
        uint2 a = *(const uint2*)&acc01[r];
        uint2 b = *(const uint2*)&acc23[r];
        float s = (__uint_as_float(a.x) + __uint_as_float(b.x)) +
                  (__uint_as_float(a.y) + __uint_as_float(b.y));
        g_xw[(row0 + (wid << 2) + r) * H1 + lane] = s;
    }
}

// ---- K4: dis = deg^-1/2 ----
__global__ void k_dis() {
    int i = blockIdx.x * blockDim.x + threadIdx.x;
    if (i < N_NODES) {
        float d = g_deg[i];
        g_dis[i] = (d > 0.f) ? rsqrtf(d) : 0.f;
    }
}

// ---- K5: GCN scatter: agg1[row] += dis[row]*dis[col]*xw[col], one warp per edge ----
__global__ void k_scatter1() {
    int t = blockIdx.x * blockDim.x + threadIdx.x;
    int e = t >> 5;
    if (e >= N_EDGES) return;
    int lane = t & 31;
    int r = g_row[e];
    int c = g_col[e];
    float w = g_dis[r] * g_dis[c];
    atomicAdd(&g_agg1[r * H1 + lane], w * g_xw[c * H1 + lane]);
}

// ---- K6: h = relu(agg1 + selfloop + b1) ----
__global__ void k_hidden(const float* __restrict__ b1) {
    int i = blockIdx.x * blockDim.x + threadIdx.x;
    if (i >= N_NODES * H1) return;
    int node = i >> 5;
    int c    = i & 31;
    float d = g_dis[node];
    float v = g_agg1[i] + d * d * g_xw[i] + __ldg(b1 + c);
    g_h[i] = fmaxf(v, 0.f);
}

// ---- K7: SAGE scatter: agg2[src] += h[dst], one warp per edge ----
__global__ void k_scatter2() {
    int t = blockIdx.x * blockDim.x + threadIdx.x;
    int e = t >> 5;
    if (e >= N_EDGES) return;
    int lane = t & 31;
    int r = g_row[e];   // src
    int c = g_col[e];   // dst
    atomicAdd(&g_agg2[r * H1 + lane], g_h[c * H1 + lane]);
}

// ---- K8: head: mean-agg, relu(h@Wl + agg@Wr + biases), L2 norm, W3, softmax ----
__global__ void __launch_bounds__(256) k_head(const float* __restrict__ Wl,
                                              const float* __restrict__ bl,
                                              const float* __restrict__ Wr,
                                              const float* __restrict__ br,
                                              const float* __restrict__ W3,
                                              const float* __restrict__ b3,
                                              float* __restrict__ out) {
    const unsigned FULL = 0xffffffffu;
    int gw   = (blockIdx.x * blockDim.x + threadIdx.x) >> 5;  // node = global warp id
    int lane = threadIdx.x & 31;
    if (gw >= N_NODES) return;

    float hv = g_h[gw * H1 + lane];
    float av = g_agg2[gw * H1 + lane];
    float cv = g_cnt[gw];
    av = (cv > 0.f) ? av / cv : 0.f;   // mean over neighbors; 0 if no out-edges

    float o = 0.f;
    if (lane < H2) o = __ldg(bl + lane) + __ldg(br + lane);
#pragma unroll
    for (int k = 0; k < H1; k++) {
        float hk = __shfl_sync(FULL, hv, k);
        float ak = __shfl_sync(FULL, av, k);
        if (lane < H2)
            o = fmaf(hk, __ldg(Wl + k * H2 + lane),
                fmaf(ak, __ldg(Wr + k * H2 + lane), o));
    }
    o = fmaxf(o, 0.f);   // lanes >= 16 hold 0

    // L2 norm over the 16 valid lanes (xor 1/2/4/8 stays within the 16-group)
    float ss = o * o;
#pragma unroll
    for (int off = 8; off > 0; off >>= 1) ss += __shfl_xor_sync(FULL, ss, off);
    float inv = 1.f / (sqrtf(ss) + 1e-6f);
    float on  = o * inv;

    // logits = on @ W3 + b3
    float l = (lane < NCLS) ? __ldg(b3 + lane) : -1e30f;
#pragma unroll
    for (int c = 0; c < H2; c++) {
        float oc = __shfl_sync(FULL, on, c);
        if (lane < NCLS) l = fmaf(oc, __ldg(W3 + c * NCLS + lane), l);
    }

    // softmax across lanes 0..6 (8-lane xor group; lane 7 = -1e30 -> exp = 0)
    float m = l;
#pragma unroll
    for (int off = 4; off > 0; off >>= 1) m = fmaxf(m, __shfl_xor_sync(FULL, m, off));
    float ev = expf(l - m);
    float sm = ev;
#pragma unroll
    for (int off = 4; off > 0; off >>= 1) sm += __shfl_xor_sync(FULL, sm, off);

    if (lane < NCLS) out[gw * NCLS + lane] = ev / sm;
}

extern "C" void kernel_launch(void* const* d_in, const int* in_sizes, int n_in,
                              void* d_out, int out_size) {
    const float* x  = (const float*)d_in[0];
    const int*   ei = (const int*)d_in[1];     // int32 view; dtype probed on device
    const float* W1 = (const float*)d_in[2];
    const float* b1 = (const float*)d_in[3];
    const float* Wl = (const float*)d_in[4];
    const float* bl = (const float*)d_in[5];
    const float* Wr = (const float*)d_in[6];
    const float* br = (const float*)d_in[7];
    const float* W3 = (const float*)d_in[8];
    const float* b3 = (const float*)d_in[9];
    float* out = (float*)d_out;

    const int T = 256;
    k_init<<<(N_NODES * H1 + T - 1) / T, T>>>();
    k_decode<<<(N_EDGES + T - 1) / T, T>>>(ei);
    k_gemm1<<<N_NODES / ROWS_PB, T>>>(x, W1);          // 384 blocks
    k_dis<<<(N_NODES + T - 1) / T, T>>>();
    k_scatter1<<<(N_EDGES * 32 + T - 1) / T, T>>>();
    k_hidden<<<(N_NODES * H1 + T - 1) / T, T>>>(b1);
    k_scatter2<<<(N_EDGES * 32 + T - 1) / T, T>>>();
    k_head<<<(N_NODES + 7) / 8, T>>>(Wl, bl, Wr, br, W3, b3, out);
}

// round 6
// speedup vs baseline: 1.3182x; 1.3182x over previous
#include <cuda_runtime.h>
#include <math.h>

#define N_NODES 12288
#define N_EDGES 196608
#define F_IN    1433
#define H1      32
#define H2      16
#define NCLS    7

#define ROWS_PB 32          // rows per block
#define KC      32          // k per chunk (= warp width)
#define NCH     12          // chunks per warp (12*32=384 >= 360 span, zero-padded)
#define KWSPAN  360         // nominal k span per warp
#define XSTR    36          // sxt row stride (mult of 4 for 16B-aligned consume)

// ---- scratch (static device globals; no allocation allowed) ----
__device__ float g_xw  [N_NODES * H1];
__device__ float g_h   [N_NODES * H1];
__device__ float g_agg1[N_NODES * H1];
__device__ float g_agg2[N_NODES * H1];
__device__ float g_deg [N_NODES];
__device__ float g_cnt [N_NODES];
__device__ int   g_row [N_EDGES];
__device__ int   g_col [N_EDGES];

typedef unsigned long long ull;

// packed f32x2 fma: acc = a*b + acc
#define FFMA2(acc, a, b) \
    asm("fma.rn.f32x2 %0, %1, %2, %0;" : "+l"(acc) : "l"(a), "l"(b))

__device__ __forceinline__ ull rep2(float v) {
    ull r; asm("mov.b64 %0, {%1, %1};" : "=l"(r) : "f"(v)); return r;
}
__device__ __forceinline__ float2 unpk(ull v) {
    float2 f; asm("mov.b64 {%0, %1}, %2;" : "=f"(f.x), "=f"(f.y) : "l"(v)); return f;
}

// ---- launch 1: zero agg1, init deg/cnt ----
__global__ void k_init_a() {
    int i = blockIdx.x * blockDim.x + threadIdx.x;
    if (i < N_NODES * H1) g_agg1[i] = 0.f;
    if (i < N_NODES) { g_deg[i] = 1.f; g_cnt[i] = 0.f; }
}
// ---- launch 2: zero agg2 ----
__global__ void k_init_b() {
    int i = blockIdx.x * blockDim.x + threadIdx.x;
    if (i < N_NODES * H1) g_agg2[i] = 0.f;
}

// ---- launch 3: probe dtype + decode indices + degree/count atomics ----
__global__ void k_decode(const int* __restrict__ ei32) {
    int v = ei32[2 * threadIdx.x + 1] | ei32[2 * threadIdx.x + 513];
    int is64 = !__syncthreads_or(v != 0);

    int e = blockIdx.x * blockDim.x + threadIdx.x;
    if (e >= N_EDGES) return;
    int r, c;
    if (is64) {
        r = ei32[2 * e];
        c = ei32[2 * (N_EDGES + e)];
    } else {
        r = ei32[e];
        c = ei32[N_EDGES + e];
    }
    g_row[e] = r;
    g_col[e] = c;
    atomicAdd(&g_deg[c], 1.f);
    atomicAdd(&g_cnt[r], 1.f);
}

// ---- launch 4 (profiled slot): xw = x @ W1 ----
// 4 warps split K; warp tile 32r x 32c, thread tile 8r x 4c.
// Per k: 2 LDS.128 (x row-pairs, FFMA2-ready) + 1 LDS.128 (w) + 4 movs + 16 FFMA2.
__global__ void __launch_bounds__(128) k_gemm1(const float* __restrict__ x,
                                               const float* __restrict__ W1) {
    __shared__ float smem[4 * KC * XSTR + 4 * KC * H1];  // sxt | sw ; sred aliases front

    const int tid  = threadIdx.x;
    const int wid  = tid >> 5;
    const int lane = tid & 31;
    const int rg   = lane >> 3;     // row group: rows rg*8 .. rg*8+7
    const int cg   = lane & 7;      // col group: cols cg*4 .. cg*4+3
    const int row0 = blockIdx.x * ROWS_PB;

    const int kbase = wid * KWSPAN;
    const int kend  = min(F_IN, kbase + KWSPAN);

    float* sxw = smem + wid * (KC * XSTR);             // [k][row]
    float* sww = smem + 4 * KC * XSTR + wid * (KC * H1); // [k][col]

    ull acc[4][4];
#pragma unroll
    for (int p = 0; p < 4; p++)
#pragma unroll
        for (int c = 0; c < 4; c++) acc[p][c] = 0ull;

    for (int ch = 0; ch < NCH; ch++) {
        const int k0 = kbase + ch * KC;
        const int kg = k0 + lane;
        const bool kin = (kg < kend);

        // stage x transposed: sxt[k=lane][row r]; coalesced LDG over k
#pragma unroll 8
        for (int r = 0; r < ROWS_PB; r++) {
            float v = kin ? __ldg(x + (size_t)(row0 + r) * F_IN + kg) : 0.f;
            sxw[lane * XSTR + r] = v;
        }
        // stage w: 1024 floats linear (zero beyond F_IN)
        const float4* wsrc = (const float4*)(W1 + (size_t)k0 * H1);
#pragma unroll
        for (int i = lane; i < KC * H1 / 4; i += 32) {
            int kk = i >> 3;
            float4 v = (k0 + kk < F_IN) ? __ldg(wsrc + i)
                                        : make_float4(0.f, 0.f, 0.f, 0.f);
            ((float4*)sww)[i] = v;
        }
        __syncwarp();

#pragma unroll 4
        for (int kk = 0; kk < KC; kk++) {
            const float* xk = sxw + kk * XSTR + rg * 8;
            ulonglong2 xa = *(const ulonglong2*)(xk);       // rows 0-3 as 2 pairs
            ulonglong2 xb = *(const ulonglong2*)(xk + 4);   // rows 4-7
            float4 wv = *(const float4*)(sww + kk * H1 + cg * 4);
            ull w0 = rep2(wv.x), w1 = rep2(wv.y), w2 = rep2(wv.z), w3 = rep2(wv.w);
            FFMA2(acc[0][0], xa.x, w0); FFMA2(acc[0][1], xa.x, w1);
            FFMA2(acc[0][2], xa.x, w2); FFMA2(acc[0][3], xa.x, w3);
            FFMA2(acc[1][0], xa.y, w0); FFMA2(acc[1][1], xa.y, w1);
            FFMA2(acc[1][2], xa.y, w2); FFMA2(acc[1][3], xa.y, w3);
            FFMA2(acc[2][0], xb.x, w0); FFMA2(acc[2][1], xb.x, w1);
            FFMA2(acc[2][2], xb.x, w2); FFMA2(acc[2][3], xb.x, w3);
            FFMA2(acc[3][0], xb.y, w0); FFMA2(acc[3][1], xb.y, w1);
            FFMA2(acc[3][2], xb.y, w2); FFMA2(acc[3][3], xb.y, w3);
        }
        __syncwarp();
    }

    // cross-warp reduction: sred[warp][row][col] aliases smem front (4096 floats)
    __syncthreads();
    float* sred = smem;
#pragma unroll
    for (int p = 0; p < 4; p++) {
        float2 v0 = unpk(acc[p][0]), v1 = unpk(acc[p][1]);
        float2 v2 = unpk(acc[p][2]), v3 = unpk(acc[p][3]);
        int re = rg * 8 + 2 * p;
        *(float4*)(sred + wid * (ROWS_PB * H1) + re * H1 + cg * 4) =
            make_float4(v0.x, v1.x, v2.x, v3.x);
        *(float4*)(sred + wid * (ROWS_PB * H1) + (re + 1) * H1 + cg * 4) =
            make_float4(v0.y, v1.y, v2.y, v3.y);
    }
    __syncthreads();

    float4* outp = (float4*)(g_xw + (size_t)row0 * H1);
    const float4* sp = (const float4*)sred;
#pragma unroll
    for (int j = tid; j < ROWS_PB * H1 / 4; j += 128) {
        float4 a = sp[j], b = sp[j + 256], c = sp[j + 512], d = sp[j + 768];
        outp[j] = make_float4(a.x + b.x + c.x + d.x, a.y + b.y + c.y + d.y,
                              a.z + b.z + c.z + d.z, a.w + b.w + c.w + d.w);
    }
}

// ---- launch 5: GCN scatter: agg1[r] += dis[r]*dis[c]*xw[c] ----
__global__ void k_scatter1() {
    int t = blockIdx.x * blockDim.x + threadIdx.x;
    int e = t >> 5;
    if (e >= N_EDGES) return;
    int lane = t & 31;
    int r = g_row[e];
    int c = g_col[e];
    float w = rsqrtf(g_deg[r]) * rsqrtf(g_deg[c]);
    atomicAdd(&g_agg1[r * H1 + lane], w * g_xw[c * H1 + lane]);
}

// ---- launch 6: h = relu(agg1 + selfloop + b1) ----
__global__ void k_hidden(const float* __restrict__ b1) {
    int i = blockIdx.x * blockDim.x + threadIdx.x;
    if (i >= N_NODES * H1) return;
    int node = i >> 5;
    int c    = i & 31;
    float d = rsqrtf(g_deg[node]);
    float v = g_agg1[i] + d * d * g_xw[i] + __ldg(b1 + c);
    g_h[i] = fmaxf(v, 0.f);
}

// ---- launch 7: SAGE scatter: agg2[src] += h[dst] ----
__global__ void k_scatter2() {
    int t = blockIdx.x * blockDim.x + threadIdx.x;
    int e = t >> 5;
    if (e >= N_EDGES) return;
    int lane = t & 31;
    int r = g_row[e];
    int c = g_col[e];
    atomicAdd(&g_agg2[r * H1 + lane], g_h[c * H1 + lane]);
}

// ---- launch 8: head ----
__global__ void __launch_bounds__(256) k_head(const float* __restrict__ Wl,
                                              const float* __restrict__ bl,
                                              const float* __restrict__ Wr,
                                              const float* __restrict__ br,
                                              const float* __restrict__ W3,
                                              const float* __restrict__ b3,
                                              float* __restrict__ out) {
    const unsigned FULL = 0xffffffffu;
    int gw   = (blockIdx.x * blockDim.x + threadIdx.x) >> 5;
    int lane = threadIdx.x & 31;
    if (gw >= N_NODES) return;

    float hv = g_h[gw * H1 + lane];
    float av = g_agg2[gw * H1 + lane];
    float cv = g_cnt[gw];
    av = (cv > 0.f) ? av / cv : 0.f;

    float o = 0.f;
    if (lane < H2) o = __ldg(bl + lane) + __ldg(br + lane);
#pragma unroll
    for (int k = 0; k < H1; k++) {
        float hk = __shfl_sync(FULL, hv, k);
        float ak = __shfl_sync(FULL, av, k);
        if (lane < H2)
            o = fmaf(hk, __ldg(Wl + k * H2 + lane),
                fmaf(ak, __ldg(Wr + k * H2 + lane), o));
    }
    o = fmaxf(o, 0.f);

    float ss = o * o;
#pragma unroll
    for (int off = 8; off > 0; off >>= 1) ss += __shfl_xor_sync(FULL, ss, off);
    float inv = 1.f / (sqrtf(ss) + 1e-6f);
    float on  = o * inv;

    float l = (lane < NCLS) ? __ldg(b3 + lane) : -1e30f;
#pragma unroll
    for (int c = 0; c < H2; c++) {
        float oc = __shfl_sync(FULL, on, c);
        if (lane < NCLS) l = fmaf(oc, __ldg(W3 + c * NCLS + lane), l);
    }

    float m = l;
#pragma unroll
    for (int off = 4; off > 0; off >>= 1) m = fmaxf(m, __shfl_xor_sync(FULL, m, off));
    float ev = expf(l - m);
    float sm = ev;
#pragma unroll
    for (int off = 4; off > 0; off >>= 1) sm += __shfl_xor_sync(FULL, sm, off);

    if (lane < NCLS) out[gw * NCLS + lane] = ev / sm;
}

extern "C" void kernel_launch(void* const* d_in, const int* in_sizes, int n_in,
                              void* d_out, int out_size) {
    const float* x  = (const float*)d_in[0];
    const int*   ei = (const int*)d_in[1];
    const float* W1 = (const float*)d_in[2];
    const float* b1 = (const float*)d_in[3];
    const float* Wl = (const float*)d_in[4];
    const float* bl = (const float*)d_in[5];
    const float* Wr = (const float*)d_in[6];
    const float* br = (const float*)d_in[7];
    const float* W3 = (const float*)d_in[8];
    const float* b3 = (const float*)d_in[9];
    float* out = (float*)d_out;

    const int T = 256;
    k_init_a<<<(N_NODES * H1 + T - 1) / T, T>>>();                 // 1
    k_init_b<<<(N_NODES * H1 + T - 1) / T, T>>>();                 // 2
    k_decode<<<(N_EDGES + T - 1) / T, T>>>(ei);                    // 3
    k_gemm1<<<N_NODES / ROWS_PB, 128>>>(x, W1);                    // 4 (profiled)
    k_scatter1<<<(N_EDGES * 32 + T - 1) / T, T>>>();               // 5
    k_hidden<<<(N_NODES * H1 + T - 1) / T, T>>>(b1);               // 6
    k_scatter2<<<(N_EDGES * 32 + T - 1) / T, T>>>();               // 7
    k_head<<<(N_NODES + 7) / 8, T>>>(Wl, bl, Wr, br, W3, b3, out); // 8
}

// round 7
// speedup vs baseline: 1.7134x; 1.2998x over previous
#include <cuda_runtime.h>
#include <math.h>

#define N_NODES 12288
#define N_EDGES 196608
#define F_IN    1433
#define H1      32
#define H2      16
#define NCLS    7

#define ROWS_PB 32          // rows per block
#define KC      32          // k per chunk (= warp width)
#define NWARP   8           // warps per block, K-split 8
#define KWSPAN  180         // k span per warp (8*180 = 1440 >= 1433)
#define NCH     6           // chunks per warp (6*32 = 192 >= 180)
#define XSTR    36          // sxt row stride (mult of 4 -> 16B-aligned consume)

// ---- scratch (static device globals; no allocation allowed) ----
__device__ float g_xw  [N_NODES * H1];
__device__ float g_h   [N_NODES * H1];
__device__ float g_agg1[N_NODES * H1];
__device__ float g_agg2[N_NODES * H1];
__device__ float g_deg [N_NODES];
__device__ float g_cnt [N_NODES];
__device__ int   g_row [N_EDGES];
__device__ int   g_col [N_EDGES];

typedef unsigned long long ull;

// packed f32x2 fma: acc = a*b + acc
#define FFMA2(acc, a, b) \
    asm("fma.rn.f32x2 %0, %1, %2, %0;" : "+l"(acc) : "l"(a), "l"(b))

__device__ __forceinline__ ull rep2(float v) {
    ull r; asm("mov.b64 %0, {%1, %1};" : "=l"(r) : "f"(v)); return r;
}
__device__ __forceinline__ float2 unpk(ull v) {
    float2 f; asm("mov.b64 {%0, %1}, %2;" : "=f"(f.x), "=f"(f.y) : "l"(v)); return f;
}
__device__ __forceinline__ void red4(float* p, float a, float b, float c, float d) {
    asm volatile("red.global.add.v4.f32 [%0], {%1, %2, %3, %4};"
                 :: "l"(p), "f"(a), "f"(b), "f"(c), "f"(d) : "memory");
}

// ---- launch 1: zero agg1, init deg/cnt ----
__global__ void k_init_a() {
    int i = blockIdx.x * blockDim.x + threadIdx.x;
    if (i < N_NODES * H1) g_agg1[i] = 0.f;
    if (i < N_NODES) { g_deg[i] = 1.f; g_cnt[i] = 0.f; }
}
// ---- launch 2: zero agg2 ----
__global__ void k_init_b() {
    int i = blockIdx.x * blockDim.x + threadIdx.x;
    if (i < N_NODES * H1) g_agg2[i] = 0.f;
}

// ---- launch 3: probe dtype + decode indices + degree/count atomics ----
__global__ void k_decode(const int* __restrict__ ei32) {
    int v = ei32[2 * threadIdx.x + 1] | ei32[2 * threadIdx.x + 513];
    int is64 = !__syncthreads_or(v != 0);

    int e = blockIdx.x * blockDim.x + threadIdx.x;
    if (e >= N_EDGES) return;
    int r, c;
    if (is64) {
        r = ei32[2 * e];
        c = ei32[2 * (N_EDGES + e)];
    } else {
        r = ei32[e];
        c = ei32[N_EDGES + e];
    }
    g_row[e] = r;
    g_col[e] = c;
    atomicAdd(&g_deg[c], 1.f);
    atomicAdd(&g_cnt[r], 1.f);
}

// ---- launch 4 (profiled slot): xw = x @ W1 ----
// 256 thr / 8 warps split K (180 each); warp tile 32r x 32c, thread tile 8r x 4c.
// x transposed in smem; W read directly via L1/L2-resident LDG.128.
#define GBODY(WV) { \
    const float* xk = sxw + kk * XSTR + rg * 8; \
    ulonglong2 xa = *(const ulonglong2*)(xk); \
    ulonglong2 xb = *(const ulonglong2*)(xk + 4); \
    ull w0 = rep2((WV).x), w1 = rep2((WV).y), w2 = rep2((WV).z), w3 = rep2((WV).w); \
    FFMA2(acc[0][0], xa.x, w0); FFMA2(acc[0][1], xa.x, w1); \
    FFMA2(acc[0][2], xa.x, w2); FFMA2(acc[0][3], xa.x, w3); \
    FFMA2(acc[1][0], xa.y, w0); FFMA2(acc[1][1], xa.y, w1); \
    FFMA2(acc[1][2], xa.y, w2); FFMA2(acc[1][3], xa.y, w3); \
    FFMA2(acc[2][0], xb.x, w0); FFMA2(acc[2][1], xb.x, w1); \
    FFMA2(acc[2][2], xb.x, w2); FFMA2(acc[2][3], xb.x, w3); \
    FFMA2(acc[3][0], xb.y, w0); FFMA2(acc[3][1], xb.y, w1); \
    FFMA2(acc[3][2], xb.y, w2); FFMA2(acc[3][3], xb.y, w3); }

__global__ void __launch_bounds__(256) k_gemm1(const float* __restrict__ x,
                                               const float* __restrict__ W1) {
    __shared__ __align__(16) float sxt[NWARP * KC * XSTR];  // 9216 floats = 36.9 KB

    const int tid  = threadIdx.x;
    const int wid  = tid >> 5;
    const int lane = tid & 31;
    const int rg   = lane >> 3;     // rows rg*8 .. rg*8+7
    const int cg   = lane & 7;      // cols cg*4 .. cg*4+3
    const int row0 = blockIdx.x * ROWS_PB;

    const int kbase = wid * KWSPAN;
    const int kend  = min(F_IN, kbase + KWSPAN);

    float* sxw = sxt + wid * (KC * XSTR);

    ull acc[4][4];
#pragma unroll
    for (int p = 0; p < 4; p++)
#pragma unroll
        for (int c = 0; c < 4; c++) acc[p][c] = 0ull;

    for (int ch = 0; ch < NCH; ch++) {
        const int k0 = kbase + ch * KC;
        const int kg = k0 + lane;
        const bool kin = (kg < kend);

        // stage x transposed: sxt[k=lane][row]; coalesced LDG over lane=k
#pragma unroll 8
        for (int r = 0; r < ROWS_PB; r++) {
            float v = kin ? __ldg(x + (size_t)(row0 + r) * F_IN + kg) : 0.f;
            sxw[lane * XSTR + r] = v;
        }
        __syncwarp();

        if (k0 + KC <= F_IN) {   // fast path: W chunk fully in range
            const float4* wp = (const float4*)(W1) + (size_t)k0 * (H1 / 4) + cg;
#pragma unroll 8
            for (int kk = 0; kk < KC; kk++) {
                float4 wv = __ldg(wp + kk * (H1 / 4));
                GBODY(wv);
            }
        } else {                 // rare tail: clamp row (x already zero there)
#pragma unroll 8
            for (int kk = 0; kk < KC; kk++) {
                int kr = min(k0 + kk, F_IN - 1);
                float4 wv = __ldg((const float4*)(W1) + (size_t)kr * (H1 / 4) + cg);
                GBODY(wv);
            }
        }
        __syncwarp();
    }

    // cross-warp reduction over 8 partials; sred aliases sxt (8192 <= 9216 floats)
    __syncthreads();
    float* sred = sxt;
#pragma unroll
    for (int p = 0; p < 4; p++) {
        float2 v0 = unpk(acc[p][0]), v1 = unpk(acc[p][1]);
        float2 v2 = unpk(acc[p][2]), v3 = unpk(acc[p][3]);
        int re = rg * 8 + 2 * p;
        *(float4*)(sred + wid * (ROWS_PB * H1) + re * H1 + cg * 4) =
            make_float4(v0.x, v1.x, v2.x, v3.x);
        *(float4*)(sred + wid * (ROWS_PB * H1) + (re + 1) * H1 + cg * 4) =
            make_float4(v0.y, v1.y, v2.y, v3.y);
    }
    __syncthreads();

    // 256 float4 outputs, one per thread; sum 8 partials
    const float4* sp = (const float4*)sred;
    float4 a = sp[tid];
#pragma unroll
    for (int w = 1; w < NWARP; w++) {
        float4 b = sp[tid + w * 256];
        a.x += b.x; a.y += b.y; a.z += b.z; a.w += b.w;
    }
    ((float4*)(g_xw + (size_t)row0 * H1))[tid] = a;
}

// ---- launch 5: GCN scatter: agg1[r] += dis[r]*dis[c]*xw[c], 8 lanes/edge, red.v4 ----
__global__ void k_scatter1() {
    int t = blockIdx.x * blockDim.x + threadIdx.x;
    int e = t >> 3;
    if (e >= N_EDGES) return;
    int g = t & 7;
    int r = g_row[e];
    int c = g_col[e];
    float w = rsqrtf(g_deg[r]) * rsqrtf(g_deg[c]);
    float4 v = *(const float4*)(g_xw + c * H1 + g * 4);
    red4(g_agg1 + r * H1 + g * 4, w * v.x, w * v.y, w * v.z, w * v.w);
}

// ---- launch 6: h = relu(agg1 + selfloop + b1) ----
__global__ void k_hidden(const float* __restrict__ b1) {
    int i = blockIdx.x * blockDim.x + threadIdx.x;
    if (i >= N_NODES * H1) return;
    int node = i >> 5;
    int c    = i & 31;
    float d = rsqrtf(g_deg[node]);
    float v = g_agg1[i] + d * d * g_xw[i] + __ldg(b1 + c);
    g_h[i] = fmaxf(v, 0.f);
}

// ---- launch 7: SAGE scatter: agg2[src] += h[dst], 8 lanes/edge, red.v4 ----
__global__ void k_scatter2() {
    int t = blockIdx.x * blockDim.x + threadIdx.x;
    int e = t >> 3;
    if (e >= N_EDGES) return;
    int g = t & 7;
    int r = g_row[e];
    int c = g_col[e];
    float4 v = *(const float4*)(g_h + c * H1 + g * 4);
    red4(g_agg2 + r * H1 + g * 4, v.x, v.y, v.z, v.w);
}

// ---- launch 8: head ----
__global__ void __launch_bounds__(256) k_head(const float* __restrict__ Wl,
                                              const float* __restrict__ bl,
                                              const float* __restrict__ Wr,
                                              const float* __restrict__ br,
                                              const float* __restrict__ W3,
                                              const float* __restrict__ b3,
                                              float* __restrict__ out) {
    const unsigned FULL = 0xffffffffu;
    int gw   = (blockIdx.x * blockDim.x + threadIdx.x) >> 5;
    int lane = threadIdx.x & 31;
    if (gw >= N_NODES) return;

    float hv = g_h[gw * H1 + lane];
    float av = g_agg2[gw * H1 + lane];
    float cv = g_cnt[gw];
    av = (cv > 0.f) ? av / cv : 0.f;

    float o = 0.f;
    if (lane < H2) o = __ldg(bl + lane) + __ldg(br + lane);
#pragma unroll
    for (int k = 0; k < H1; k++) {
        float hk = __shfl_sync(FULL, hv, k);
        float ak = __shfl_sync(FULL, av, k);
        if (lane < H2)
            o = fmaf(hk, __ldg(Wl + k * H2 + lane),
                fmaf(ak, __ldg(Wr + k * H2 + lane), o));
    }
    o = fmaxf(o, 0.f);

    float ss = o * o;
#pragma unroll
    for (int off = 8; off > 0; off >>= 1) ss += __shfl_xor_sync(FULL, ss, off);
    float inv = 1.f / (sqrtf(ss) + 1e-6f);
    float on  = o * inv;

    float l = (lane < NCLS) ? __ldg(b3 + lane) : -1e30f;
#pragma unroll
    for (int c = 0; c < H2; c++) {
        float oc = __shfl_sync(FULL, on, c);
        if (lane < NCLS) l = fmaf(oc, __ldg(W3 + c * NCLS + lane), l);
    }

    float m = l;
#pragma unroll
    for (int off = 4; off > 0; off >>= 1) m = fmaxf(m, __shfl_xor_sync(FULL, m, off));
    float ev = expf(l - m);
    float sm = ev;
#pragma unroll
    for (int off = 4; off > 0; off >>= 1) sm += __shfl_xor_sync(FULL, sm, off);

    if (lane < NCLS) out[gw * NCLS + lane] = ev / sm;
}

extern "C" void kernel_launch(void* const* d_in, const int* in_sizes, int n_in,
                              void* d_out, int out_size) {
    const float* x  = (const float*)d_in[0];
    const int*   ei = (const int*)d_in[1];
    const float* W1 = (const float*)d_in[2];
    const float* b1 = (const float*)d_in[3];
    const float* Wl = (const float*)d_in[4];
    const float* bl = (const float*)d_in[5];
    const float* Wr = (const float*)d_in[6];
    const float* br = (const float*)d_in[7];
    const float* W3 = (const float*)d_in[8];
    const float* b3 = (const float*)d_in[9];
    float* out = (float*)d_out;

    const int T = 256;
    k_init_a<<<(N_NODES * H1 + T - 1) / T, T>>>();                 // 1
    k_init_b<<<(N_NODES * H1 + T - 1) / T, T>>>();                 // 2
    k_decode<<<(N_EDGES + T - 1) / T, T>>>(ei);                    // 3
    k_gemm1<<<N_NODES / ROWS_PB, 256>>>(x, W1);                    // 4 (profiled)
    k_scatter1<<<(N_EDGES * 8 + T - 1) / T, T>>>();                // 5
    k_hidden<<<(N_NODES * H1 + T - 1) / T, T>>>(b1);               // 6
    k_scatter2<<<(N_EDGES * 8 + T - 1) / T, T>>>();                // 7
    k_head<<<(N_NODES + 7) / 8, T>>>(Wl, bl, Wr, br, W3, b3, out); // 8
}

// round 8
// speedup vs baseline: 1.9214x; 1.1214x over previous
#include <cuda_runtime.h>
#include <math.h>

#define N_NODES 12288
#define N_EDGES 196608
#define F_IN    1433
#define H1      32
#define H2      16
#define NCLS    7

#define ROWS_PB 32          // rows per block
#define KC      32          // k per chunk (= warp width)
#define NWARP   8           // warps per block, K-split 8
#define KWSPAN  180         // k span per warp (8*180 = 1440 >= 1433)
#define NCH     6           // chunks per warp (6*32 = 192 >= 180)
#define XSTR    36          // sxt row stride (mult of 4 -> 16B-aligned consume)

// ---- scratch (static device globals; no allocation allowed) ----
__device__ float g_xw  [N_NODES * H1];
__device__ float g_h   [N_NODES * H1];
__device__ float g_agg1[N_NODES * H1];
__device__ float g_agg2[N_NODES * H1];
__device__ float g_deg [N_NODES];
__device__ float g_cnt [N_NODES];
__device__ int   g_row [N_EDGES];
__device__ int   g_col [N_EDGES];

typedef unsigned long long ull;

// packed f32x2 fma: acc = a*b + acc
#define FFMA2(acc, a, b) \
    asm("fma.rn.f32x2 %0, %1, %2, %0;" : "+l"(acc) : "l"(a), "l"(b))

__device__ __forceinline__ ull rep2(float v) {
    ull r; asm("mov.b64 %0, {%1, %1};" : "=l"(r) : "f"(v)); return r;
}
__device__ __forceinline__ float2 unpk(ull v) {
    float2 f; asm("mov.b64 {%0, %1}, %2;" : "=f"(f.x), "=f"(f.y) : "l"(v)); return f;
}
__device__ __forceinline__ void red4(float* p, float a, float b, float c, float d) {
    asm volatile("red.global.add.v4.f32 [%0], {%1, %2, %3, %4};"
                 :: "l"(p), "f"(a), "f"(b), "f"(c), "f"(d) : "memory");
}

// ---- launch 1: zero agg1, init deg/cnt ----
__global__ void k_init_a() {
    int i = blockIdx.x * blockDim.x + threadIdx.x;
    if (i < N_NODES * H1) g_agg1[i] = 0.f;
    if (i < N_NODES) { g_deg[i] = 1.f; g_cnt[i] = 0.f; }
}
// ---- launch 2: zero agg2 ----
__global__ void k_init_b() {
    int i = blockIdx.x * blockDim.x + threadIdx.x;
    if (i < N_NODES * H1) g_agg2[i] = 0.f;
}

// ---- launch 3: probe dtype + decode indices + degree/count atomics ----
__global__ void k_decode(const int* __restrict__ ei32) {
    int v = ei32[2 * threadIdx.x + 1] | ei32[2 * threadIdx.x + 513];
    int is64 = !__syncthreads_or(v != 0);

    int e = blockIdx.x * blockDim.x + threadIdx.x;
    if (e >= N_EDGES) return;
    int r, c;
    if (is64) {
        r = ei32[2 * e];
        c = ei32[2 * (N_EDGES + e)];
    } else {
        r = ei32[e];
        c = ei32[N_EDGES + e];
    }
    g_row[e] = r;
    g_col[e] = c;
    atomicAdd(&g_deg[c], 1.f);
    atomicAdd(&g_cnt[r], 1.f);
}

// ---- launch 4 (profiled slot): xw = x @ W1 ----
// 256 thr / 8 warps split K (180 each); warp tile 32r x 32c, thread tile 8r x 4c.
// x staged via register-prefetch software pipeline (32 LDG in flight during
// compute of previous chunk); W read per-kk via L1-resident LDG.128.
#define GBODY(WV) { \
    const float* xk = sxw + kk * XSTR + rg * 8; \
    ulonglong2 xa = *(const ulonglong2*)(xk); \
    ulonglong2 xb = *(const ulonglong2*)(xk + 4); \
    ull w0 = rep2((WV).x), w1 = rep2((WV).y), w2 = rep2((WV).z), w3 = rep2((WV).w); \
    FFMA2(acc[0][0], xa.x, w0); FFMA2(acc[0][1], xa.x, w1); \
    FFMA2(acc[0][2], xa.x, w2); FFMA2(acc[0][3], xa.x, w3); \
    FFMA2(acc[1][0], xa.y, w0); FFMA2(acc[1][1], xa.y, w1); \
    FFMA2(acc[1][2], xa.y, w2); FFMA2(acc[1][3], xa.y, w3); \
    FFMA2(acc[2][0], xb.x, w0); FFMA2(acc[2][1], xb.x, w1); \
    FFMA2(acc[2][2], xb.x, w2); FFMA2(acc[2][3], xb.x, w3); \
    FFMA2(acc[3][0], xb.y, w0); FFMA2(acc[3][1], xb.y, w1); \
    FFMA2(acc[3][2], xb.y, w2); FFMA2(acc[3][3], xb.y, w3); }

__global__ void __launch_bounds__(256) k_gemm1(const float* __restrict__ x,
                                               const float* __restrict__ W1) {
    __shared__ __align__(16) float sxt[NWARP * KC * XSTR];  // 9216 floats = 36.9 KB

    const int tid  = threadIdx.x;
    const int wid  = tid >> 5;
    const int lane = tid & 31;
    const int rg   = lane >> 3;     // rows rg*8 .. rg*8+7
    const int cg   = lane & 7;      // cols cg*4 .. cg*4+3
    const int row0 = blockIdx.x * ROWS_PB;

    const int kbase = wid * KWSPAN;
    const int kend  = min(F_IN, kbase + KWSPAN);

    float* sxw = sxt + wid * (KC * XSTR);
    const float* xrow = x + (size_t)row0 * F_IN;

    ull acc[4][4];
#pragma unroll
    for (int p = 0; p < 4; p++)
#pragma unroll
        for (int c = 0; c < 4; c++) acc[p][c] = 0ull;

    // prologue: prefetch chunk 0 into registers
    float v[ROWS_PB];
    {
        const int kg = kbase + lane;
        const bool kin = (kg < kend);
#pragma unroll
        for (int r = 0; r < ROWS_PB; r++)
            v[r] = kin ? __ldg(xrow + (size_t)r * F_IN + kg) : 0.f;
    }

    for (int ch = 0; ch < NCH; ch++) {
        // commit prefetched chunk to smem (transposed: sxt[k=lane][row])
#pragma unroll
        for (int r = 0; r < ROWS_PB; r++)
            sxw[lane * XSTR + r] = v[r];
        __syncwarp();

        // prefetch next chunk while computing this one
        {
            const int kg = kbase + (ch + 1) * KC + lane;
            const bool kin = (ch + 1 < NCH) && (kg < kend);
#pragma unroll
            for (int r = 0; r < ROWS_PB; r++)
                v[r] = kin ? __ldg(xrow + (size_t)r * F_IN + kg) : 0.f;
        }

        const int k0 = kbase + ch * KC;
        if (k0 + KC <= F_IN) {   // fast path: W chunk fully in range
            const float4* wp = (const float4*)(W1) + (size_t)k0 * (H1 / 4) + cg;
#pragma unroll 8
            for (int kk = 0; kk < KC; kk++) {
                float4 wv = __ldg(wp + kk * (H1 / 4));
                GBODY(wv);
            }
        } else {                 // rare tail: clamp row (x already zero there)
#pragma unroll 8
            for (int kk = 0; kk < KC; kk++) {
                int kr = min(k0 + kk, F_IN - 1);
                float4 wv = __ldg((const float4*)(W1) + (size_t)kr * (H1 / 4) + cg);
                GBODY(wv);
            }
        }
        __syncwarp();
    }

    // cross-warp reduction over 8 partials; sred aliases sxt (8192 <= 9216 floats)
    __syncthreads();
    float* sred = sxt;
#pragma unroll
    for (int p = 0; p < 4; p++) {
        float2 v0 = unpk(acc[p][0]), v1 = unpk(acc[p][1]);
        float2 v2 = unpk(acc[p][2]), v3 = unpk(acc[p][3]);
        int re = rg * 8 + 2 * p;
        *(float4*)(sred + wid * (ROWS_PB * H1) + re * H1 + cg * 4) =
            make_float4(v0.x, v1.x, v2.x, v3.x);
        *(float4*)(sred + wid * (ROWS_PB * H1) + (re + 1) * H1 + cg * 4) =
            make_float4(v0.y, v1.y, v2.y, v3.y);
    }
    __syncthreads();

    // 256 float4 outputs, one per thread; sum 8 partials
    const float4* sp = (const float4*)sred;
    float4 a = sp[tid];
#pragma unroll
    for (int w = 1; w < NWARP; w++) {
        float4 b = sp[tid + w * 256];
        a.x += b.x; a.y += b.y; a.z += b.z; a.w += b.w;
    }
    ((float4*)(g_xw + (size_t)row0 * H1))[tid] = a;
}

// ---- launch 5: GCN scatter: agg1[r] += dis[r]*dis[c]*xw[c], 8 lanes/edge, red.v4 ----
__global__ void k_scatter1() {
    int t = blockIdx.x * blockDim.x + threadIdx.x;
    int e = t >> 3;
    if (e >= N_EDGES) return;
    int g = t & 7;
    int r = g_row[e];
    int c = g_col[e];
    float w = rsqrtf(g_deg[r]) * rsqrtf(g_deg[c]);
    float4 v = *(const float4*)(g_xw + c * H1 + g * 4);
    red4(g_agg1 + r * H1 + g * 4, w * v.x, w * v.y, w * v.z, w * v.w);
}

// ---- launch 6: h = relu(agg1 + selfloop + b1) ----
__global__ void k_hidden(const float* __restrict__ b1) {
    int i = blockIdx.x * blockDim.x + threadIdx.x;
    if (i >= N_NODES * H1) return;
    int node = i >> 5;
    int c    = i & 31;
    float d = rsqrtf(g_deg[node]);
    float v = g_agg1[i] + d * d * g_xw[i] + __ldg(b1 + c);
    g_h[i] = fmaxf(v, 0.f);
}

// ---- launch 7: SAGE scatter: agg2[src] += h[dst], 8 lanes/edge, red.v4 ----
__global__ void k_scatter2() {
    int t = blockIdx.x * blockDim.x + threadIdx.x;
    int e = t >> 3;
    if (e >= N_EDGES) return;
    int g = t & 7;
    int r = g_row[e];
    int c = g_col[e];
    float4 v = *(const float4*)(g_h + c * H1 + g * 4);
    red4(g_agg2 + r * H1 + g * 4, v.x, v.y, v.z, v.w);
}

// ---- launch 8: head ----
__global__ void __launch_bounds__(256) k_head(const float* __restrict__ Wl,
                                              const float* __restrict__ bl,
                                              const float* __restrict__ Wr,
                                              const float* __restrict__ br,
                                              const float* __restrict__ W3,
                                              const float* __restrict__ b3,
                                              float* __restrict__ out) {
    const unsigned FULL = 0xffffffffu;
    int gw   = (blockIdx.x * blockDim.x + threadIdx.x) >> 5;
    int lane = threadIdx.x & 31;
    if (gw >= N_NODES) return;

    float hv = g_h[gw * H1 + lane];
    float av = g_agg2[gw * H1 + lane];
    float cv = g_cnt[gw];
    av = (cv > 0.f) ? av / cv : 0.f;

    float o = 0.f;
    if (lane < H2) o = __ldg(bl + lane) + __ldg(br + lane);
#pragma unroll
    for (int k = 0; k < H1; k++) {
        float hk = __shfl_sync(FULL, hv, k);
        float ak = __shfl_sync(FULL, av, k);
        if (lane < H2)
            o = fmaf(hk, __ldg(Wl + k * H2 + lane),
                fmaf(ak, __ldg(Wr + k * H2 + lane), o));
    }
    o = fmaxf(o, 0.f);

    float ss = o * o;
#pragma unroll
    for (int off = 8; off > 0; off >>= 1) ss += __shfl_xor_sync(FULL, ss, off);
    float inv = 1.f / (sqrtf(ss) + 1e-6f);
    float on  = o * inv;

    float l = (lane < NCLS) ? __ldg(b3 + lane) : -1e30f;
#pragma unroll
    for (int c = 0; c < H2; c++) {
        float oc = __shfl_sync(FULL, on, c);
        if (lane < NCLS) l = fmaf(oc, __ldg(W3 + c * NCLS + lane), l);
    }

    float m = l;
#pragma unroll
    for (int off = 4; off > 0; off >>= 1) m = fmaxf(m, __shfl_xor_sync(FULL, m, off));
    float ev = expf(l - m);
    float sm = ev;
#pragma unroll
    for (int off = 4; off > 0; off >>= 1) sm += __shfl_xor_sync(FULL, sm, off);

    if (lane < NCLS) out[gw * NCLS + lane] = ev / sm;
}

extern "C" void kernel_launch(void* const* d_in, const int* in_sizes, int n_in,
                              void* d_out, int out_size) {
    const float* x  = (const float*)d_in[0];
    const int*   ei = (const int*)d_in[1];
    const float* W1 = (const float*)d_in[2];
    const float* b1 = (const float*)d_in[3];
    const float* Wl = (const float*)d_in[4];
    const float* bl = (const float*)d_in[5];
    const float* Wr = (const float*)d_in[6];
    const float* br = (const float*)d_in[7];
    const float* W3 = (const float*)d_in[8];
    const float* b3 = (const float*)d_in[9];
    float* out = (float*)d_out;

    const int T = 256;
    k_init_a<<<(N_NODES * H1 + T - 1) / T, T>>>();                 // 1
    k_init_b<<<(N_NODES * H1 + T - 1) / T, T>>>();                 // 2
    k_decode<<<(N_EDGES + T - 1) / T, T>>>(ei);                    // 3
    k_gemm1<<<N_NODES / ROWS_PB, 256>>>(x, W1);                    // 4 (profiled)
    k_scatter1<<<(N_EDGES * 8 + T - 1) / T, T>>>();                // 5
    k_hidden<<<(N_NODES * H1 + T - 1) / T, T>>>(b1);               // 6
    k_scatter2<<<(N_EDGES * 8 + T - 1) / T, T>>>();                // 7
    k_head<<<(N_NODES + 7) / 8, T>>>(Wl, bl, Wr, br, W3, b3, out); // 8
}